// round 6
// baseline (speedup 1.0000x reference)
#include <cuda_runtime.h>
#include <cuda_fp16.h>
#include <math.h>
#include <stdint.h>

#define NJ    24
#define DIN   256
#define NTOK  1152
#define MROWS 18432
#define EPSV  1e-6f

#define M_CTA 96
#define AST   264          /* A smem row stride (halves) */
#define CST   770          /* C smem row stride (halves) */
#define BST   40           /* B stage row stride (halves) */
#define A_OFF    0                         /* 96*264*2   = 50688  */
#define C_OFF    50688                     /* 96*770*2   = 147840 */
#define B_OFF    198528                    /* 2*128*40*2 = 20480  */
#define BIAS_OFF 219008                    /* 768*4      = 3072   */
#define SMEM_TOT 222080
#define B_STAGE_BYTES 10240

__device__ __half g_wt[3 * DIN * DIN];     /* [sel*256+n][k] transposed fp16 */

/* ---------------- W transpose+convert (tiny) ---------------- */
__global__ __launch_bounds__(256) void wcvt_kernel(
    const float* __restrict__ Wq, const float* __restrict__ Wk, const float* __restrict__ Wv)
{
    int e  = blockIdx.x * 256 + threadIdx.x;
    int ws = e >> 16;
    int r  = e & 65535;
    int n  = r >> 8;
    int k  = r & 255;
    const float* W = (ws == 0) ? Wq : (ws == 1 ? Wk : Wv);
    g_wt[ws * 65536 + n * 256 + k] = __float2half_rn(W[k * 256 + n]);
}

/* ---------------- PTX helpers ---------------- */
__device__ __forceinline__ void mma16816(float* c, const uint32_t* a, const uint32_t* b) {
    asm volatile("mma.sync.aligned.m16n8k16.row.col.f32.f16.f16.f32 "
        "{%0,%1,%2,%3}, {%4,%5,%6,%7}, {%8,%9}, {%0,%1,%2,%3};"
        : "+f"(c[0]), "+f"(c[1]), "+f"(c[2]), "+f"(c[3])
        : "r"(a[0]), "r"(a[1]), "r"(a[2]), "r"(a[3]), "r"(b[0]), "r"(b[1]));
}
__device__ __forceinline__ void ldsm_x4(uint32_t* r, uint32_t addr) {
    asm volatile("ldmatrix.sync.aligned.m8n8.x4.shared.b16 {%0,%1,%2,%3}, [%4];"
        : "=r"(r[0]), "=r"(r[1]), "=r"(r[2]), "=r"(r[3]) : "r"(addr));
}
__device__ __forceinline__ void cp16(uint32_t dst, const void* src) {
    asm volatile("cp.async.cg.shared.global [%0], [%1], 16;" :: "r"(dst), "l"(src));
}
#define CP_COMMIT() asm volatile("cp.async.commit_group;" ::: "memory")
#define CP_WAIT(n)  asm volatile("cp.async.wait_group %0;" :: "n"(n) : "memory")
__device__ __forceinline__ uint32_t smem_u32(const void* p) {
    uint32_t a;
    asm("{ .reg .u64 t; cvta.to.shared.u64 t, %1; cvt.u32.u64 %0, t; }" : "=r"(a) : "l"(p));
    return a;
}

/* ---------------- fused projection + block-diag attention ----------------
 * CTA = 96 rows (4 frames). A (x slice) resident fp16 in smem; N looped in
 * 6x128 chunks with k32 double-buffered B staging; C = QKV fp16 in smem;
 * attention per (frame,head) warp-pair reads C, writes out directly.
 */
__global__ __launch_bounds__(256) void fused_kernel(
    const float* __restrict__ x,
    const float* __restrict__ bq, const float* __restrict__ bk, const float* __restrict__ bv,
    float* __restrict__ out)
{
    extern __shared__ char smc[];
    const uint32_t sb = smem_u32(smc);
    __half* Ch = (__half*)(smc + C_OFF);
    float* sbias = (float*)(smc + BIAS_OFF);

    const int tid  = threadIdx.x;
    const int wid  = tid >> 5, lane = tid & 31;
    const int gid  = lane >> 2, tig = lane & 3;
    const int m0   = blockIdx.x * M_CTA;
    const int mwarp = wid & 1;              /* 2 m-warps x 4 n-warps */
    const int nwarp = wid >> 1;

    const int mq = lane >> 3;
    const int laneRowA = (mq & 1) * 8 + (lane & 7);
    const int laneColA = (mq >> 1) * 8;
    const int laneRowB = (mq >> 1) * 8 + (lane & 7);
    const int laneColB = (mq & 1) * 8;

    /* B stage issue: thread t -> row t>>1, 32B halfspan (t&1) */
    auto stageB = [&](int s) {
        const int nc = s >> 3, kc = s & 7;
        const __half* src = g_wt + (size_t)(nc * 128 + (tid >> 1)) * 256 + kc * 32 + (tid & 1) * 16;
        uint32_t dst = sb + B_OFF + (uint32_t)(s & 1) * B_STAGE_BYTES
                     + (uint32_t)(tid >> 1) * 80 + (tid & 1) * 32;
        cp16(dst,      src);
        cp16(dst + 16, src + 8);
    };

    stageB(0);
    CP_COMMIT();

    /* A: load x slice fp32, convert to fp16 smem [96][AST] */
#pragma unroll
    for (int i = 0; i < 24; i++) {
        int idx = i * 256 + tid;
        int row = idx >> 6, c4 = idx & 63;
        float4 v = *(const float4*)(x + (size_t)(m0 + row) * 256 + c4 * 4);
        __half* ap = (__half*)smc + row * AST + c4 * 4;
        *(__half2*)ap       = __floats2half2_rn(v.x, v.y);
        *(__half2*)(ap + 2) = __floats2half2_rn(v.z, v.w);
    }
    sbias[tid]       = bq[tid];
    sbias[256 + tid] = bk[tid];
    sbias[512 + tid] = bv[tid];

    float c[3][4][4];

#pragma unroll 1
    for (int s = 0; s < 48; s++) {
        if (s < 47) { stageB(s + 1); CP_COMMIT(); CP_WAIT(1); }
        else        { CP_WAIT(0); }
        __syncthreads();

        if ((s & 7) == 0) {
#pragma unroll
            for (int mf = 0; mf < 3; mf++)
#pragma unroll
                for (int nf = 0; nf < 4; nf++)
#pragma unroll
                    for (int q = 0; q < 4; q++) c[mf][nf][q] = 0.f;
        }

        const uint32_t bbase = sb + B_OFF + (uint32_t)(s & 1) * B_STAGE_BYTES;
#pragma unroll
        for (int ks2 = 0; ks2 < 2; ks2++) {
            const int kg = (s & 7) * 32 + ks2 * 16;
            uint32_t a[3][4];
#pragma unroll
            for (int mf = 0; mf < 3; mf++) {
                uint32_t ao = (uint32_t)((mwarp * 48 + mf * 16 + laneRowA) * AST
                                         + kg + laneColA) * 2;
                ldsm_x4(a[mf], sb + A_OFF + ao);
            }
#pragma unroll
            for (int ntp = 0; ntp < 2; ntp++) {
                uint32_t bo = (uint32_t)((nwarp * 32 + ntp * 16 + laneRowB) * BST
                                         + ks2 * 16 + laneColB) * 2;
                uint32_t bfr[4];
                ldsm_x4(bfr, bbase + bo);
#pragma unroll
                for (int mf = 0; mf < 3; mf++) {
                    mma16816(c[mf][2 * ntp],     a[mf], bfr);
                    mma16816(c[mf][2 * ntp + 1], a[mf], bfr + 2);
                }
            }
        }
        __syncthreads();

        if ((s & 7) == 7) {                  /* epilogue for n-chunk nc */
            const int nc = s >> 3, sel = nc >> 1, ncol0 = nc * 128;
#pragma unroll
            for (int mf = 0; mf < 3; mf++) {
                int m = mwarp * 48 + mf * 16 + gid;
#pragma unroll
                for (int nf = 0; nf < 4; nf++) {
                    int gcol = ncol0 + nwarp * 32 + nf * 8 + tig * 2;
                    float bi0 = sbias[gcol], bi1 = sbias[gcol + 1];
                    float v0 = c[mf][nf][0] + bi0, v1 = c[mf][nf][1] + bi1;
                    float v2 = c[mf][nf][2] + bi0, v3 = c[mf][nf][3] + bi1;
                    if (sel == 2) {
                        v0 = fmaxf(v0, 0.f); v1 = fmaxf(v1, 0.f);
                        v2 = fmaxf(v2, 0.f); v3 = fmaxf(v3, 0.f);
                    }
                    *(__half2*)(Ch + (size_t)m * CST + gcol)       = __floats2half2_rn(v0, v1);
                    *(__half2*)(Ch + (size_t)(m + 8) * CST + gcol) = __floats2half2_rn(v2, v3);
                }
            }
        }
    }
    __syncthreads();

    /* ---------- attention: warp w handles pairs w, w+8, w+16, w+24 ---------- */
#define SWST 28
    float* sc = (float*)smc + wid * 32 * SWST;   /* reuse A region: 8*3584 <= 50688 */
    const float scale = 0.17677669529663688f;    /* 1/sqrt(32) */

#pragma unroll 1
    for (int it = 0; it < 4; it++) {
        const int pid = wid + it * 8;
        const int f = pid >> 3, h = pid & 7;
        const int rowbase = f * NJ;

        /* q^T into scratch: sc[d][i] = q[i][d] */
        const __half* qp = Ch + (size_t)rowbase * CST + h * 32;
#pragma unroll
        for (int r = 0; r < NJ; r++)
            sc[lane * SWST + r] = __half2float(qp[r * CST + lane]);
        __syncwarp();

        /* scores: lane j holds K row */
        const int j = (lane < NJ) ? lane : 0;
        float kreg[32];
        {
            const __half* kp = Ch + (size_t)(rowbase + j) * CST + 256 + h * 32;
#pragma unroll
            for (int cc = 0; cc < 16; cc++) {
                __half2 hv = *(const __half2*)(kp + cc * 2);
                float2 fv = __half22float2(hv);
                kreg[2 * cc] = fv.x; kreg[2 * cc + 1] = fv.y;
            }
        }
        float s[NJ];
#pragma unroll
        for (int i = 0; i < NJ; i++) s[i] = 0.f;
#pragma unroll
        for (int d = 0; d < 32; d++) {
            float kd = kreg[d];
#pragma unroll
            for (int i4 = 0; i4 < 6; i4++) {
                float4 q4 = *(const float4*)&sc[d * SWST + i4 * 4];
                s[i4*4+0] = fmaf(q4.x, kd, s[i4*4+0]);
                s[i4*4+1] = fmaf(q4.y, kd, s[i4*4+1]);
                s[i4*4+2] = fmaf(q4.z, kd, s[i4*4+2]);
                s[i4*4+3] = fmaf(q4.w, kd, s[i4*4+3]);
            }
        }
#pragma unroll
        for (int i = 0; i < NJ; i++)
            s[i] = (lane < NJ) ? s[i] * scale : -3.402823466e38f;

        /* softmax over lanes (keys); eps in denominator like reference */
        __syncwarp();
        float w_[NJ];
#pragma unroll
        for (int i = 0; i < NJ; i++) {
            float m = s[i];
#pragma unroll
            for (int off = 16; off > 0; off >>= 1)
                m = fmaxf(m, __shfl_xor_sync(0xffffffffu, m, off));
            float e = __expf(s[i] - m);
            float sum = e;
#pragma unroll
            for (int off = 16; off > 0; off >>= 1)
                sum += __shfl_xor_sync(0xffffffffu, sum, off);
            w_[i] = e / (sum + EPSV);
        }

        if (lane < NJ) {
#pragma unroll
            for (int i = 0; i < NJ; i++)
                sc[lane * SWST + i] = w_[i];
        }
        __syncwarp();

        /* o[i][d] = sum_j w(i,j) v[j][d]; lane = d */
        float vreg[NJ];
#pragma unroll
        for (int jj = 0; jj < NJ; jj++)
            vreg[jj] = __half2float(Ch[(size_t)(rowbase + jj) * CST + 512 + h * 32 + lane]);
        float o[NJ];
#pragma unroll
        for (int i = 0; i < NJ; i++) o[i] = 0.f;
#pragma unroll
        for (int jj = 0; jj < NJ; jj++) {
            float vj = vreg[jj];
#pragma unroll
            for (int i4 = 0; i4 < 6; i4++) {
                float4 a4 = *(const float4*)&sc[jj * SWST + i4 * 4];
                o[i4*4+0] = fmaf(a4.x, vj, o[i4*4+0]);
                o[i4*4+1] = fmaf(a4.y, vj, o[i4*4+1]);
                o[i4*4+2] = fmaf(a4.z, vj, o[i4*4+2]);
                o[i4*4+3] = fmaf(a4.w, vj, o[i4*4+3]);
            }
        }

        float* od = out + (size_t)(m0 + f * NJ) * DIN + h * 32 + lane;
#pragma unroll
        for (int i = 0; i < NJ; i++)
            od[(size_t)i * DIN] = o[i];
        __syncwarp();
    }
}

/* ---------------- launch ---------------- */
extern "C" void kernel_launch(void* const* d_in, const int* in_sizes, int n_in,
                              void* d_out, int out_size)
{
    const float* x  = (const float*)d_in[0];
    const float* Wq = (const float*)d_in[1];
    const float* bq = (const float*)d_in[2];
    const float* Wk = (const float*)d_in[3];
    const float* bk = (const float*)d_in[4];
    const float* Wv = (const float*)d_in[5];
    const float* bv = (const float*)d_in[6];
    float* out = (float*)d_out;

    wcvt_kernel<<<768, 256>>>(Wq, Wk, Wv);

    cudaFuncSetAttribute(fused_kernel, cudaFuncAttributeMaxDynamicSharedMemorySize, SMEM_TOT);
    fused_kernel<<<MROWS / M_CTA, 256, SMEM_TOT>>>(x, bq, bk, bv, out);
}

// round 7
// speedup vs baseline: 1.8113x; 1.8113x over previous
#include <cuda_runtime.h>
#include <cuda_fp16.h>
#include <math.h>
#include <stdint.h>

#define NJ    24
#define DIN   256
#define NTOK  1152
#define MROWS 18432
#define EPSV  1e-6f

__device__ __half g_wt[3 * DIN * DIN];                      /* [sel*256+n][k] fp16 */
__device__ __half g_qkv[3ull * 16 * 8 * NTOK * 32];         /* [sel*128+b*8+h][tok][32] fp16 */

/* ---------------- W transpose+convert: 32x32 smem tiles ---------------- */
__global__ __launch_bounds__(256) void wcvt_kernel(
    const float* __restrict__ Wq, const float* __restrict__ Wk, const float* __restrict__ Wv)
{
    __shared__ float t[32][33];
    const int sel = blockIdx.z;
    const float* W = (sel == 0) ? Wq : (sel == 1 ? Wk : Wv);
    const int n0 = blockIdx.x * 32, k0 = blockIdx.y * 32;
    const int tx = threadIdx.x, ty = threadIdx.y;
#pragma unroll
    for (int i = 0; i < 4; i++)
        t[ty + i * 8][tx] = W[(size_t)(k0 + ty + i * 8) * 256 + n0 + tx];
    __syncthreads();
#pragma unroll
    for (int i = 0; i < 4; i++)
        g_wt[sel * 65536 + (size_t)(n0 + ty + i * 8) * 256 + k0 + tx] =
            __float2half_rn(t[tx][ty + i * 8]);
}

/* ---------------- PTX helpers ---------------- */
__device__ __forceinline__ void mma16816(float* c, const uint32_t* a, const uint32_t* b) {
    asm volatile("mma.sync.aligned.m16n8k16.row.col.f32.f16.f16.f32 "
        "{%0,%1,%2,%3}, {%4,%5,%6,%7}, {%8,%9}, {%0,%1,%2,%3};"
        : "+f"(c[0]), "+f"(c[1]), "+f"(c[2]), "+f"(c[3])
        : "r"(a[0]), "r"(a[1]), "r"(a[2]), "r"(a[3]), "r"(b[0]), "r"(b[1]));
}
__device__ __forceinline__ void ldsm_x4(uint32_t* r, uint32_t addr) {
    asm volatile("ldmatrix.sync.aligned.m8n8.x4.shared.b16 {%0,%1,%2,%3}, [%4];"
        : "=r"(r[0]), "=r"(r[1]), "=r"(r[2]), "=r"(r[3]) : "r"(addr));
}
__device__ __forceinline__ void cp16(uint32_t dst, const void* src) {
    asm volatile("cp.async.cg.shared.global [%0], [%1], 16;" :: "r"(dst), "l"(src));
}
#define CP_COMMIT() asm volatile("cp.async.commit_group;" ::: "memory")
#define CP_WAIT(n)  asm volatile("cp.async.wait_group %0;" :: "n"(n) : "memory")
__device__ __forceinline__ uint32_t smem_u32(const void* p) {
    uint32_t a;
    asm("{ .reg .u64 t; cvta.to.shared.u64 t, %1; cvt.u32.u64 %0, t; }" : "=r"(a) : "l"(p));
    return a;
}

/* ---------------- fp16 GEMM: resident A + double-buffered B ----------------
 * C[18432,768] = x @ Wcat^T. CTA 128 rows x one 128-col n-chunk. 8 warps (4m x 2n),
 * warp tile 32x64. A: fp32 loaded once, fp16-resident smem [128][264].
 * B: k64 chunks, cp.async double-buffered, row stride 72 halves.
 */
#define AST 264
#define A_BYTES   (128 * AST * 2)        /* 67584 */
#define B_STAGE   (128 * 72 * 2)         /* 18432 */
#define B_OFF     A_BYTES
#define BIAS_OFF  (A_BYTES + 2 * B_STAGE)           /* 104448 */
#define SMEM_GEMM (BIAS_OFF + 128 * 4)              /* 104960 -> 2 CTAs/SM */

__global__ __launch_bounds__(256) void gemm_kernel(
    const float* __restrict__ x,
    const float* __restrict__ bq, const float* __restrict__ bk, const float* __restrict__ bv)
{
    extern __shared__ char smc[];
    const uint32_t sb = smem_u32(smc);
    __half* Ah = (__half*)smc;
    float* sbias = (float*)(smc + BIAS_OFF);

    const int tid  = threadIdx.x;
    const int wid  = tid >> 5, lane = tid & 31;
    const int gid  = lane >> 2, tig = lane & 3;
    const int m0   = blockIdx.x * 128;
    const int nc   = blockIdx.y;                 /* 0..5 */
    const int ncol0 = nc * 128;
    const int sel  = nc >> 1;
    const int rbase = (wid & 3) * 32;
    const int nbase = (wid >> 2) * 64;

    const int mq = lane >> 3;
    const int laneRowA = (mq & 1) * 8 + (lane & 7);
    const int laneColA = (mq >> 1) * 8;
    const int laneRowB = (mq >> 1) * 8 + (lane & 7);
    const int laneColB = (mq & 1) * 8;

    auto stageB = [&](int ch, int s) {
        const __half* src = g_wt + (size_t)(ncol0 + (tid >> 1)) * 256 + ch * 64 + (tid & 1) * 32;
        uint32_t dst = sb + B_OFF + (uint32_t)s * B_STAGE + (uint32_t)(tid >> 1) * 144 + (tid & 1) * 64;
        cp16(dst,      src);
        cp16(dst + 16, src + 8);
        cp16(dst + 32, src + 16);
        cp16(dst + 48, src + 24);
    };

    stageB(0, 0);
    CP_COMMIT();

    /* A prologue: fp32 -> fp16 resident tile */
#pragma unroll
    for (int i = 0; i < 32; i++) {
        int idx = i * 256 + tid;
        int row = idx >> 6, c4 = idx & 63;
        float4 v = *(const float4*)(x + (size_t)(m0 + row) * 256 + c4 * 4);
        __half2 h0 = __floats2half2_rn(v.x, v.y);
        __half2 h1 = __floats2half2_rn(v.z, v.w);
        uint2 pk;
        pk.x = *(uint32_t*)&h0;
        pk.y = *(uint32_t*)&h1;
        *(uint2*)(Ah + row * AST + c4 * 4) = pk;
    }
    if (tid < 128) {
        const float* bp = (sel == 0) ? bq : (sel == 1 ? bk : bv);
        sbias[tid] = bp[(nc & 1) * 128 + tid];
    }

    float c[2][8][4];
#pragma unroll
    for (int mt = 0; mt < 2; mt++)
#pragma unroll
        for (int nt = 0; nt < 8; nt++)
#pragma unroll
            for (int q = 0; q < 4; q++) c[mt][nt][q] = 0.f;

    for (int ch = 0; ch < 4; ch++) {
        const int s = ch & 1;
        if (ch < 3) { stageB(ch + 1, s ^ 1); CP_COMMIT(); CP_WAIT(1); }
        else        { CP_WAIT(0); }
        __syncthreads();

        const uint32_t bBase = sb + B_OFF + (uint32_t)s * B_STAGE;
#pragma unroll
        for (int ks = 0; ks < 4; ks++) {
            uint32_t a[2][4];
#pragma unroll
            for (int mt = 0; mt < 2; mt++) {
                uint32_t ao = (uint32_t)((rbase + mt * 16 + laneRowA) * AST
                                         + ch * 64 + ks * 16 + laneColA) * 2;
                ldsm_x4(a[mt], sb + ao);
            }
#pragma unroll
            for (int ntp = 0; ntp < 4; ntp++) {
                uint32_t bo = (uint32_t)((nbase + ntp * 16 + laneRowB) * 72
                                         + ks * 16 + laneColB) * 2;
                uint32_t bfr[4];
                ldsm_x4(bfr, bBase + bo);
#pragma unroll
                for (int mt = 0; mt < 2; mt++) {
                    mma16816(c[mt][2 * ntp],     a[mt], bfr);
                    mma16816(c[mt][2 * ntp + 1], a[mt], bfr + 2);
                }
            }
        }
        __syncthreads();
    }

    /* epilogue: bias (+relu on V), fp16 head-major */
    const int bb = m0 / NTOK;
    const int tokbase = m0 % NTOK;
    __half* outsel = g_qkv + (size_t)(sel * 128 + bb * 8) * NTOK * 32;

#pragma unroll
    for (int mt = 0; mt < 2; mt++) {
        int r0 = tokbase + rbase + mt * 16 + gid;
#pragma unroll
        for (int nt = 0; nt < 8; nt++) {
            int cl = nbase + nt * 8 + tig * 2;               /* 0..127 */
            int colsel = (nc & 1) * 128 + cl;                /* 0..255 within sel */
            int h = colsel >> 5, d = colsel & 31;
            float bi0 = sbias[cl], bi1 = sbias[cl + 1];
            float v0 = c[mt][nt][0] + bi0, v1 = c[mt][nt][1] + bi1;
            float v2 = c[mt][nt][2] + bi0, v3 = c[mt][nt][3] + bi1;
            if (sel == 2) {
                v0 = fmaxf(v0, 0.f); v1 = fmaxf(v1, 0.f);
                v2 = fmaxf(v2, 0.f); v3 = fmaxf(v3, 0.f);
            }
            __half* p0 = outsel + ((size_t)h * NTOK + r0) * 32 + d;
            *(__half2*)p0            = __floats2half2_rn(v0, v1);
            *(__half2*)(p0 + 8 * 32) = __floats2half2_rn(v2, v3);
        }
    }
}

/* ---------------- attention: warp per (b, h, frame), fp16 QKV in ---------- */
#define SWST 28

__global__ __launch_bounds__(256) void attn_kernel(float* __restrict__ out)
{
    __shared__ float sw[8 * 32 * SWST];
    const int bh   = blockIdx.x;
    const int wid  = threadIdx.x >> 5;
    const int lane = threadIdx.x & 31;
    const int frame = blockIdx.y * 8 + wid;

    const __half* qb = g_qkv + ((size_t)bh * NTOK + (size_t)frame * NJ) * 32;
    const __half* kb = g_qkv + ((size_t)(128 + bh) * NTOK + (size_t)frame * NJ) * 32;
    const __half* vb = g_qkv + ((size_t)(256 + bh) * NTOK + (size_t)frame * NJ) * 32;

    float* sc = sw + wid * 32 * SWST;

#pragma unroll
    for (int r = 0; r < NJ; r++)
        sc[lane * SWST + r] = __half2float(qb[r * 32 + lane]);
    __syncwarp();

    const int j = (lane < NJ) ? lane : 0;
    float kreg[32];
    {
        const __half2* kp = (const __half2*)(kb + j * 32);
#pragma unroll
        for (int cc = 0; cc < 16; cc++) {
            float2 fv = __half22float2(kp[cc]);
            kreg[2 * cc] = fv.x; kreg[2 * cc + 1] = fv.y;
        }
    }
    float s[NJ];
#pragma unroll
    for (int i = 0; i < NJ; i++) s[i] = 0.f;
#pragma unroll
    for (int d = 0; d < 32; d++) {
        float kd = kreg[d];
#pragma unroll
        for (int i4 = 0; i4 < 6; i4++) {
            float4 q4 = *(const float4*)&sc[d * SWST + i4 * 4];
            s[i4*4+0] = fmaf(q4.x, kd, s[i4*4+0]);
            s[i4*4+1] = fmaf(q4.y, kd, s[i4*4+1]);
            s[i4*4+2] = fmaf(q4.z, kd, s[i4*4+2]);
            s[i4*4+3] = fmaf(q4.w, kd, s[i4*4+3]);
        }
    }
    const float scale = 0.17677669529663688f;
#pragma unroll
    for (int i = 0; i < NJ; i++)
        s[i] = (lane < NJ) ? s[i] * scale : -3.402823466e38f;

    __syncwarp();
    float w_[NJ];
#pragma unroll
    for (int i = 0; i < NJ; i++) {
        float m = s[i];
#pragma unroll
        for (int off = 16; off > 0; off >>= 1)
            m = fmaxf(m, __shfl_xor_sync(0xffffffffu, m, off));
        float e = __expf(s[i] - m);
        float sum = e;
#pragma unroll
        for (int off = 16; off > 0; off >>= 1)
            sum += __shfl_xor_sync(0xffffffffu, sum, off);
        w_[i] = e / (sum + EPSV);
    }

    if (lane < NJ) {
#pragma unroll
        for (int i = 0; i < NJ; i++)
            sc[lane * SWST + i] = w_[i];
    }
    __syncwarp();

    float vreg[NJ];
#pragma unroll
    for (int jj = 0; jj < NJ; jj++)
        vreg[jj] = __half2float(vb[jj * 32 + lane]);
    float o[NJ];
#pragma unroll
    for (int i = 0; i < NJ; i++) o[i] = 0.f;
#pragma unroll
    for (int jj = 0; jj < NJ; jj++) {
        float vj = vreg[jj];
#pragma unroll
        for (int i4 = 0; i4 < 6; i4++) {
            float4 a4 = *(const float4*)&sc[jj * SWST + i4 * 4];
            o[i4*4+0] = fmaf(a4.x, vj, o[i4*4+0]);
            o[i4*4+1] = fmaf(a4.y, vj, o[i4*4+1]);
            o[i4*4+2] = fmaf(a4.z, vj, o[i4*4+2]);
            o[i4*4+3] = fmaf(a4.w, vj, o[i4*4+3]);
        }
    }

    const int b = bh >> 3, h = bh & 7;
    float* od = out + ((size_t)b * NTOK + (size_t)frame * NJ) * DIN + h * 32 + lane;
#pragma unroll
    for (int i = 0; i < NJ; i++)
        od[(size_t)i * DIN] = o[i];
}

/* ---------------- launch ---------------- */
extern "C" void kernel_launch(void* const* d_in, const int* in_sizes, int n_in,
                              void* d_out, int out_size)
{
    const float* x  = (const float*)d_in[0];
    const float* Wq = (const float*)d_in[1];
    const float* bq = (const float*)d_in[2];
    const float* Wk = (const float*)d_in[3];
    const float* bk = (const float*)d_in[4];
    const float* Wv = (const float*)d_in[5];
    const float* bv = (const float*)d_in[6];
    float* out = (float*)d_out;

    wcvt_kernel<<<dim3(8, 8, 3), dim3(32, 8)>>>(Wq, Wk, Wv);

    cudaFuncSetAttribute(gemm_kernel, cudaFuncAttributeMaxDynamicSharedMemorySize, SMEM_GEMM);
    gemm_kernel<<<dim3(144, 6), 256, SMEM_GEMM>>>(x, bq, bk, bv);

    attn_kernel<<<dim3(128, 6), 256>>>(out);
}